// round 2
// baseline (speedup 1.0000x reference)
#include <cuda_runtime.h>
#include <math.h>

// ---------------- problem constants ----------------
#define S_    8
#define B_    128
#define N_    32
#define D_    1024
#define HEADS_ 16
#define DH_   64
#define Q_    64
#define INNER_ 1024
#define KVW_  2048           // 2*INNER
#define FFH_  4096           // INNER*MULT
#define FF2_  8192           // INNER*MULT*2
#define ROWS_ (S_*N_*Q_)     // 16384 rows for LN/FF
#define KVROWS_ (S_*N_*B_)   // 32768 rows for kv gemm

// ---------------- scratch (device globals; no allocation allowed) -------
__device__ float g_kv [(size_t)S_*N_*B_*KVW_];    // 268 MB  (S,N,B,2048)
__device__ float g_att[(size_t)ROWS_*INNER_];     // 67 MB   (S,N,Q,1024)
__device__ float g_y  [(size_t)ROWS_*INNER_];     // 67 MB
__device__ float g_u  [(size_t)ROWS_*FF2_];       // 537 MB
__device__ float g_h  [(size_t)ROWS_*FFH_];       // 268 MB

// ---------------- generic tiled fp32 GEMM ----------------
// C[M,N] = A[M,K] @ B[K,N] (+ epilogue per mode)
// mode 0: A rows remapped from x's (S,B,N,D) layout to (S,N,B) row order
// mode 1: += bias[n]
// mode 2: += bias[n] + addmat[m*N+n]
#define BM 128
#define BN 128
#define BK 16
#define TM 8
#define TN 8

__global__ __launch_bounds__(256) void gemm_kernel(
    const float* __restrict__ A, const float* __restrict__ Bm,
    float* __restrict__ C, int M, int Nn, int K,
    int mode, const float* __restrict__ bias, const float* __restrict__ addmat)
{
    __shared__ float As[BK][BM];
    __shared__ float Bs[BK][BN];
    const int tid  = threadIdx.x;
    const int row0 = blockIdx.y * BM;
    const int col0 = blockIdx.x * BN;
    const int tx = tid % (BN / TN);   // 0..15
    const int ty = tid / (BN / TN);   // 0..15

    float acc[TM][TN];
    #pragma unroll
    for (int i = 0; i < TM; i++)
        #pragma unroll
        for (int j = 0; j < TN; j++) acc[i][j] = 0.f;

    for (int k0 = 0; k0 < K; k0 += BK) {
        // load A tile (transpose into As[k][m])
        #pragma unroll
        for (int t = tid; t < BM * BK; t += 256) {
            int ml = t / BK, kl = t % BK;
            int m = row0 + ml;
            const float* arow;
            if (mode == 0) {
                // m = ((s*32+n)*128+b) ; A row lives at x[s][b][n][:]
                int s  = m >> 12;        // /4096
                int rm = m & 4095;
                int n  = rm >> 7;        // /128
                int b  = rm & 127;
                arow = A + ((size_t)((s * 128 + b) * 32 + n)) * 1024;
            } else {
                arow = A + (size_t)m * K;
            }
            As[kl][ml] = arow[k0 + kl];
        }
        // load B tile (coalesced)
        #pragma unroll
        for (int t = tid; t < BK * BN; t += 256) {
            int kl = t / BN, nl = t % BN;
            Bs[kl][nl] = Bm[(size_t)(k0 + kl) * Nn + col0 + nl];
        }
        __syncthreads();

        #pragma unroll
        for (int k = 0; k < BK; k++) {
            float ra[TM], rb[TN];
            #pragma unroll
            for (int i = 0; i < TM; i++) ra[i] = As[k][ty * TM + i];
            #pragma unroll
            for (int j = 0; j < TN; j++) rb[j] = Bs[k][tx * TN + j];
            #pragma unroll
            for (int i = 0; i < TM; i++)
                #pragma unroll
                for (int j = 0; j < TN; j++)
                    acc[i][j] += ra[i] * rb[j];
        }
        __syncthreads();
    }

    #pragma unroll
    for (int i = 0; i < TM; i++) {
        int m = row0 + ty * TM + i;
        float* crow = C + (size_t)m * Nn;
        #pragma unroll
        for (int j = 0; j < TN; j++) {
            int n = col0 + tx * TN + j;
            float v = acc[i][j];
            if (mode == 1)      v += bias[n];
            else if (mode == 2) v += bias[n] + addmat[(size_t)m * Nn + n];
            crow[n] = v;
        }
    }
}

// ---------------- fused attention per (s,n,h) ----------------
// smem: sQ[64*64], sKV[128*65] (padded), sS[64*128]
#define ATTN_SMEM ((Q_*DH_ + B_*65 + Q_*B_) * (int)sizeof(float))

__global__ __launch_bounds__(256) void attn_kernel(
    const float* __restrict__ q, const int* __restrict__ mask)
{
    extern __shared__ float sm[];
    float* sQ  = sm;                 // 64x64
    float* sKV = sQ + Q_ * DH_;      // 128x65 (padded rows)
    float* sS  = sKV + B_ * 65;      // 64x128

    const int blk = blockIdx.x;
    const int s = blk / (N_ * HEADS_);
    const int n = (blk / HEADS_) % N_;
    const int h = blk % HEADS_;
    const int tid = threadIdx.x;

    // load Q head
    for (int t = tid; t < Q_ * DH_; t += 256) {
        int qi = t >> 6, d = t & 63;
        sQ[t] = q[qi * INNER_ + h * DH_ + d];
    }
    // load K head
    const float* kvbase = g_kv + ((size_t)(s * N_ + n)) * B_ * KVW_;
    for (int t = tid; t < B_ * DH_; t += 256) {
        int j = t >> 6, d = t & 63;
        sKV[j * 65 + d] = kvbase[(size_t)j * KVW_ + h * DH_ + d];
    }
    __syncthreads();

    // sim = (Q @ K^T) * scale, masked
    for (int t = tid; t < Q_ * B_; t += 256) {
        int qi = t >> 7, j = t & 127;
        const float* qp = sQ + qi * DH_;
        const float* kp = sKV + j * 65;
        float a = 0.f;
        #pragma unroll
        for (int d = 0; d < DH_; d++) a += qp[d] * kp[d];
        a *= 0.125f;                               // DH^-0.5
        if (mask[s * B_ + j] == 0) a = -1e10f;
        sS[qi * 128 + j] = a;
    }
    __syncthreads();

    // softmax over j (128): 8 warps x 8 rows
    const int warp = tid >> 5, lane = tid & 31;
    for (int r = warp * 8; r < warp * 8 + 8; r++) {
        float* row = sS + r * 128;
        float v0 = row[lane], v1 = row[lane + 32], v2 = row[lane + 64], v3 = row[lane + 96];
        float mx = fmaxf(fmaxf(v0, v1), fmaxf(v2, v3));
        #pragma unroll
        for (int o = 16; o > 0; o >>= 1) mx = fmaxf(mx, __shfl_xor_sync(0xffffffffu, mx, o));
        v0 = expf(v0 - mx); v1 = expf(v1 - mx); v2 = expf(v2 - mx); v3 = expf(v3 - mx);
        float sum = v0 + v1 + v2 + v3;
        #pragma unroll
        for (int o = 16; o > 0; o >>= 1) sum += __shfl_xor_sync(0xffffffffu, sum, o);
        float inv = 1.0f / sum;
        row[lane] = v0 * inv; row[lane + 32] = v1 * inv;
        row[lane + 64] = v2 * inv; row[lane + 96] = v3 * inv;
    }
    __syncthreads();

    // load V head over K's buffer
    for (int t = tid; t < B_ * DH_; t += 256) {
        int j = t >> 6, d = t & 63;
        sKV[j * 65 + d] = kvbase[(size_t)j * KVW_ + INNER_ + h * DH_ + d];
    }
    __syncthreads();

    // out = attn @ V
    float* outbase = g_att + ((size_t)(s * N_ + n)) * Q_ * INNER_;
    for (int t = tid; t < Q_ * DH_; t += 256) {
        int qi = t >> 6, d = t & 63;
        const float* ar = sS + qi * 128;
        float a = 0.f;
        #pragma unroll
        for (int j = 0; j < B_; j++) a += ar[j] * sKV[j * 65 + d];
        outbase[(size_t)qi * INNER_ + h * DH_ + d] = a;
    }
}

// ---------------- LayerNorm (one block per row of 1024) ----------------
__global__ __launch_bounds__(256) void ln_kernel(
    const float* __restrict__ gamma, const float* __restrict__ beta)
{
    const int r = blockIdx.x;
    const float* xr = g_att + (size_t)r * INNER_;
    float* yr = g_y + (size_t)r * INNER_;
    const int tid = threadIdx.x;
    const int warp = tid >> 5, lane = tid & 31;

    float v[4];
    float sum = 0.f;
    #pragma unroll
    for (int i = 0; i < 4; i++) { v[i] = xr[tid + i * 256]; sum += v[i]; }

    __shared__ float red[8];
    #pragma unroll
    for (int o = 16; o > 0; o >>= 1) sum += __shfl_xor_sync(0xffffffffu, sum, o);
    if (lane == 0) red[warp] = sum;
    __syncthreads();
    float tot = red[lane & 7];
    #pragma unroll
    for (int o = 4; o > 0; o >>= 1) tot += __shfl_xor_sync(0xffffffffu, tot, o);
    // every thread now has the full sum (groups of 8 lanes each reduced all 8 entries)
    float mean = tot * (1.0f / 1024.0f);

    float sq = 0.f;
    #pragma unroll
    for (int i = 0; i < 4; i++) { float d = v[i] - mean; sq += d * d; }
    #pragma unroll
    for (int o = 16; o > 0; o >>= 1) sq += __shfl_xor_sync(0xffffffffu, sq, o);
    __syncthreads();
    if (lane == 0) red[warp] = sq;
    __syncthreads();
    float tot2 = red[lane & 7];
    #pragma unroll
    for (int o = 4; o > 0; o >>= 1) tot2 += __shfl_xor_sync(0xffffffffu, tot2, o);
    float var = tot2 * (1.0f / 1024.0f);
    float inv = rsqrtf(var + 1e-5f);

    #pragma unroll
    for (int i = 0; i < 4; i++) {
        int c = tid + i * 256;
        yr[c] = (v[i] - mean) * inv * gamma[c] + beta[c];
    }
}

// ---------------- GEGLU: h = a * gelu_exact(g) ----------------
__global__ __launch_bounds__(256) void geglu_kernel()
{
    size_t i = (size_t)blockIdx.x * 256 + threadIdx.x;   // over 16384*4096
    size_t r = i >> 12;
    int c = (int)(i & 4095);
    float a = g_u[r * FF2_ + c];
    float g = g_u[r * FF2_ + FFH_ + c];
    float ge = 0.5f * g * (1.0f + erff(g * 0.70710678118654752f));
    g_h[i] = a * ge;
}

// ---------------- launch ----------------
extern "C" void kernel_launch(void* const* d_in, const int* in_sizes, int n_in,
                              void* d_out, int out_size)
{
    const float* x    = (const float*)d_in[0];
    const int*   mask = (const int*)  d_in[1];
    const float* q    = (const float*)d_in[2];
    const float* W_kv = (const float*)d_in[3];
    const float* ln_g = (const float*)d_in[4];
    const float* ln_b = (const float*)d_in[5];
    const float* W1   = (const float*)d_in[6];
    const float* b1   = (const float*)d_in[7];
    const float* W2   = (const float*)d_in[8];
    const float* b2   = (const float*)d_in[9];
    float* out = (float*)d_out;

    float *kv, *att, *y, *u, *h;
    cudaGetSymbolAddress((void**)&kv,  g_kv);
    cudaGetSymbolAddress((void**)&att, g_att);
    cudaGetSymbolAddress((void**)&y,   g_y);
    cudaGetSymbolAddress((void**)&u,   g_u);
    cudaGetSymbolAddress((void**)&h,   g_h);
    (void)att; (void)in_sizes; (void)n_in; (void)out_size;

    cudaFuncSetAttribute(attn_kernel,
                         cudaFuncAttributeMaxDynamicSharedMemorySize, ATTN_SMEM);

    // 1) kv = x_t @ W_kv           (32768 x 2048, K=1024)
    {
        dim3 grid(KVW_ / BN, KVROWS_ / BM);
        gemm_kernel<<<grid, 256>>>(x, W_kv, kv, KVROWS_, KVW_, D_, 0, nullptr, nullptr);
    }
    // 2) fused attention -> g_att
    attn_kernel<<<S_ * N_ * HEADS_, 256, ATTN_SMEM>>>(q, mask);
    // 3) LayerNorm -> g_y
    ln_kernel<<<ROWS_, 256>>>(ln_g, ln_b);
    // 4) u = y @ W1 + b1           (16384 x 8192, K=1024)
    {
        dim3 grid(FF2_ / BN, ROWS_ / BM);
        gemm_kernel<<<grid, 256>>>(y, W1, u, ROWS_, FF2_, INNER_, 1, b1, nullptr);
    }
    // 5) geglu -> g_h
    geglu_kernel<<<(ROWS_ * (size_t)FFH_) / 256, 256>>>();
    // 6) out = h @ W2 + b2 + y     (16384 x 1024, K=4096)
    {
        dim3 grid(INNER_ / BN, ROWS_ / BM);
        gemm_kernel<<<grid, 256>>>(h, W2, out, ROWS_, INNER_, FFH_, 2, b2, y);
    }
}

// round 4
// speedup vs baseline: 3.8990x; 3.8990x over previous
#include <cuda_runtime.h>
#include <cuda_bf16.h>
#include <math.h>
#include <stdint.h>

// ---------------- problem constants ----------------
#define S_     8
#define B_     128
#define N_     32
#define D_     1024
#define HEADS_ 16
#define DH_    64
#define Q_     64
#define INNER_ 1024
#define KVW_   2048          // 2*INNER
#define FFH_   4096          // INNER*MULT
#define FF2_   8192          // INNER*MULT*2
#define ROWS_  (S_*N_*Q_)    // 16384
#define KVROWS_ (S_*N_*B_)   // 32768

// ---------------- scratch (device globals) ----------------
__device__ float g_kv [(size_t)KVROWS_*KVW_];     // 268 MB
__device__ float g_att[(size_t)ROWS_*INNER_];     // 67 MB
__device__ float g_y  [(size_t)ROWS_*INNER_];     // 67 MB
__device__ float g_u  [(size_t)ROWS_*FF2_];       // 537 MB

__device__ __nv_bfloat16 g_xa_hi[(size_t)KVROWS_*D_];
__device__ __nv_bfloat16 g_xa_lo[(size_t)KVROWS_*D_];
__device__ __nv_bfloat16 g_wkt_hi[(size_t)KVW_*D_];
__device__ __nv_bfloat16 g_wkt_lo[(size_t)KVW_*D_];
__device__ __nv_bfloat16 g_w1t_hi[(size_t)FF2_*INNER_];
__device__ __nv_bfloat16 g_w1t_lo[(size_t)FF2_*INNER_];
__device__ __nv_bfloat16 g_w2t_hi[(size_t)INNER_*FFH_];
__device__ __nv_bfloat16 g_w2t_lo[(size_t)INNER_*FFH_];
__device__ __nv_bfloat16 g_y_hi [(size_t)ROWS_*INNER_];
__device__ __nv_bfloat16 g_y_lo [(size_t)ROWS_*INNER_];
__device__ __nv_bfloat16 g_h_hi [(size_t)ROWS_*FFH_];
__device__ __nv_bfloat16 g_h_lo [(size_t)ROWS_*FFH_];

// ---------------- helpers ----------------
__device__ __forceinline__ uint32_t smem_u32(const void* p) {
    uint32_t a;
    asm("{ .reg .u64 t; cvta.to.shared.u64 t, %1; cvt.u32.u64 %0, t; }" : "=r"(a) : "l"(p));
    return a;
}
#define SW128(b) ((b) ^ (((b) >> 3) & 0x70))

__device__ __forceinline__ void ldsm_x4(uint32_t (&r)[4], uint32_t a) {
    asm volatile("ldmatrix.sync.aligned.m8n8.x4.shared.b16 {%0,%1,%2,%3}, [%4];"
        : "=r"(r[0]), "=r"(r[1]), "=r"(r[2]), "=r"(r[3]) : "r"(a));
}
__device__ __forceinline__ void mma16816(float (&c)[4], const uint32_t (&a)[4],
                                         uint32_t b0, uint32_t b1) {
    asm volatile("mma.sync.aligned.m16n8k16.row.col.f32.bf16.bf16.f32 "
        "{%0,%1,%2,%3}, {%4,%5,%6,%7}, {%8,%9}, {%0,%1,%2,%3};"
        : "+f"(c[0]), "+f"(c[1]), "+f"(c[2]), "+f"(c[3])
        : "r"(a[0]), "r"(a[1]), "r"(a[2]), "r"(a[3]), "r"(b0), "r"(b1));
}
__device__ __forceinline__ void split2(float v, __nv_bfloat16& h, __nv_bfloat16& l) {
    h = __float2bfloat16(v);
    l = __float2bfloat16(v - __bfloat162float(h));
}

// ---------------- bf16x3 split GEMM via mma.sync ----------------
// C[M,Nn] = A[M,K] @ B^T ; A as (Ah,Al) [M][K] bf16, B as (Bh,Bl) [Nn][K] bf16
// mode 0: plain; 1: +bias[n]; 2: +bias[n]+addmat[m][n]
#define BKC 64                       // K per chunk
#define TILE_B 16384                 // 128 rows x 128 bytes
#define STAGE_B (4*TILE_B)           // Ah, Al, Bh, Bl
#define GEMM_SMEM (1024 + 2*STAGE_B) // 2 stages + alignment pad

__global__ __launch_bounds__(256) void mma_gemm(
    const __nv_bfloat16* __restrict__ Ah, const __nv_bfloat16* __restrict__ Al,
    const __nv_bfloat16* __restrict__ Bh, const __nv_bfloat16* __restrict__ Bl,
    float* __restrict__ C, int Nn, int K, int mode,
    const float* __restrict__ bias, const float* __restrict__ addmat)
{
    extern __shared__ char smem[];
    const uint32_t tiles = (smem_u32(smem) + 1023u) & ~1023u;
    const int tid = threadIdx.x;
    const int wid = tid >> 5, lid = tid & 31;
    const int row0 = blockIdx.y * 128;
    const int col0 = blockIdx.x * 128;
    const int wm = wid & 1;          // 2 M-groups of 64
    const int wn = wid >> 1;         // 4 N-groups of 32

    const __nv_bfloat16* a0 = Ah + (size_t)row0 * K;
    const __nv_bfloat16* a1 = Al + (size_t)row0 * K;
    const __nv_bfloat16* b0 = Bh + (size_t)col0 * K;
    const __nv_bfloat16* b1 = Bl + (size_t)col0 * K;

    const int nch = K / BKC;

    auto load_stage = [&](int st, int kc) {
        const uint32_t sb = tiles + st * STAGE_B;
        const int kB = kc * BKC * 2;          // byte offset in K
        #pragma unroll
        for (int j = 0; j < 4; j++) {
            const int i = j * 256 + tid;      // 0..1023
            const int r = i >> 3;             // 0..127
            const int c = i & 7;              // 16B chunk
            const uint32_t d = (uint32_t)(r * 128 + ((c * 16) ^ ((r & 7) * 16)));
            const size_t go = (size_t)r * K * 2 + kB + c * 16;
            asm volatile("cp.async.cg.shared.global [%0], [%1], 16;"
                :: "r"(sb + d), "l"((const char*)a0 + go));
            asm volatile("cp.async.cg.shared.global [%0], [%1], 16;"
                :: "r"(sb + TILE_B + d), "l"((const char*)a1 + go));
            asm volatile("cp.async.cg.shared.global [%0], [%1], 16;"
                :: "r"(sb + 2*TILE_B + d), "l"((const char*)b0 + go));
            asm volatile("cp.async.cg.shared.global [%0], [%1], 16;"
                :: "r"(sb + 3*TILE_B + d), "l"((const char*)b1 + go));
        }
        asm volatile("cp.async.commit_group;" ::: "memory");
    };

    float acc[4][4][4];
    #pragma unroll
    for (int i = 0; i < 4; i++)
        #pragma unroll
        for (int j = 0; j < 4; j++)
            #pragma unroll
            for (int t = 0; t < 4; t++) acc[i][j][t] = 0.f;

    const int lr = lid & 7;          // ldmatrix row within 8x8
    const int g  = lid >> 3;         // matrix group 0..3
    const uint32_t laneXor = (uint32_t)(lr * 16);

    load_stage(0, 0);
    load_stage(1, 1);

    for (int kc = 0; kc < nch; kc++) {
        asm volatile("cp.async.wait_group 1;" ::: "memory");
        __syncthreads();

        const uint32_t sb = tiles + (kc & 1) * STAGE_B;
        #pragma unroll
        for (int kk = 0; kk < 4; kk++) {
            const uint32_t cx = (uint32_t)((kk * 32 + (g >> 1) * 16)) ^ laneXor;
            uint32_t ah[4][4], al[4][4];
            #pragma unroll
            for (int i = 0; i < 4; i++) {
                const uint32_t row = (uint32_t)(wm * 64 + i * 16 + lr + (g & 1) * 8);
                const uint32_t off = row * 128 + cx;
                ldsm_x4(ah[i], sb + off);
                ldsm_x4(al[i], sb + TILE_B + off);
            }
            uint32_t bh[2][4], bl[2][4];
            #pragma unroll
            for (int jj = 0; jj < 2; jj++) {
                const uint32_t row = (uint32_t)(wn * 32 + jj * 16 + lr + (g & 1) * 8);
                const uint32_t off = row * 128 + cx;
                ldsm_x4(bh[jj], sb + 2*TILE_B + off);
                ldsm_x4(bl[jj], sb + 3*TILE_B + off);
            }
            #pragma unroll
            for (int i = 0; i < 4; i++) {
                #pragma unroll
                for (int jj = 0; jj < 2; jj++) {
                    mma16816(acc[i][2*jj],   ah[i], bh[jj][0], bh[jj][2]);
                    mma16816(acc[i][2*jj],   ah[i], bl[jj][0], bl[jj][2]);
                    mma16816(acc[i][2*jj],   al[i], bh[jj][0], bh[jj][2]);
                    mma16816(acc[i][2*jj+1], ah[i], bh[jj][1], bh[jj][3]);
                    mma16816(acc[i][2*jj+1], ah[i], bl[jj][1], bl[jj][3]);
                    mma16816(acc[i][2*jj+1], al[i], bh[jj][1], bh[jj][3]);
                }
            }
        }
        __syncthreads();
        if (kc + 2 < nch) load_stage(kc & 1, kc + 2);
    }

    // epilogue
    const int lr4 = lid >> 2, lc2 = (lid & 3) * 2;
    #pragma unroll
    for (int i = 0; i < 4; i++) {
        #pragma unroll
        for (int j = 0; j < 4; j++) {
            const int mr = row0 + wm * 64 + i * 16 + lr4;
            const int cc = col0 + wn * 32 + j * 8 + lc2;
            float2 v0 = make_float2(acc[i][j][0], acc[i][j][1]);
            float2 v1 = make_float2(acc[i][j][2], acc[i][j][3]);
            if (mode >= 1) {
                v0.x += bias[cc];     v0.y += bias[cc + 1];
                v1.x += bias[cc];     v1.y += bias[cc + 1];
            }
            if (mode == 2) {
                const float* am0 = addmat + (size_t)mr * Nn + cc;
                const float* am1 = addmat + (size_t)(mr + 8) * Nn + cc;
                v0.x += am0[0]; v0.y += am0[1];
                v1.x += am1[0]; v1.y += am1[1];
            }
            *(float2*)(C + (size_t)mr * Nn + cc) = v0;
            *(float2*)(C + (size_t)(mr + 8) * Nn + cc) = v1;
        }
    }
}

// ---------------- prep: x (remap rows) -> bf16 hi/lo ----------------
__global__ __launch_bounds__(256) void prep_x_kernel(const float* __restrict__ x)
{
    const size_t i = (size_t)blockIdx.x * 256 + threadIdx.x;
    const size_t e = i << 2;
    const int m = (int)(e >> 10);
    const int col = (int)(e & 1023);
    const int s = m >> 12, rm = m & 4095, n = rm >> 7, b = rm & 127;
    const float4 v = *(const float4*)(x + (((size_t)((s * 128 + b) * 32 + n)) << 10) + col);
    __nv_bfloat16 h0, l0, h1, l1, h2, l2, h3, l3;
    split2(v.x, h0, l0); split2(v.y, h1, l1);
    split2(v.z, h2, l2); split2(v.w, h3, l3);
    *(__nv_bfloat162*)(g_xa_hi + e)     = __halves2bfloat162(h0, h1);
    *(__nv_bfloat162*)(g_xa_hi + e + 2) = __halves2bfloat162(h2, h3);
    *(__nv_bfloat162*)(g_xa_lo + e)     = __halves2bfloat162(l0, l1);
    *(__nv_bfloat162*)(g_xa_lo + e + 2) = __halves2bfloat162(l2, l3);
}

// ---------------- prep: transpose W [R][C] -> [C][R] bf16 hi/lo ----------------
__global__ __launch_bounds__(256) void tsplit_kernel(
    const float* __restrict__ in, __nv_bfloat16* __restrict__ oh,
    __nv_bfloat16* __restrict__ ol, int R, int C)
{
    __shared__ float tile[32][33];
    const int r0 = blockIdx.y * 32, c0 = blockIdx.x * 32;
    const int tx = threadIdx.x, ty = threadIdx.y;
    #pragma unroll
    for (int j = ty; j < 32; j += 8)
        tile[j][tx] = in[(size_t)(r0 + j) * C + c0 + tx];
    __syncthreads();
    #pragma unroll
    for (int j = ty; j < 32; j += 8) {
        const float v = tile[tx][j];
        __nv_bfloat16 h, l;
        split2(v, h, l);
        const size_t o = (size_t)(c0 + j) * R + r0 + tx;
        oh[o] = h; ol[o] = l;
    }
}

// ---------------- fused attention per (s,n,h) ----------------
#define ATTN_SMEM ((Q_*DH_ + B_*65 + Q_*B_) * (int)sizeof(float))

__global__ __launch_bounds__(256) void attn_kernel(
    const float* __restrict__ q, const int* __restrict__ mask)
{
    extern __shared__ float sm[];
    float* sQ  = sm;
    float* sKV = sQ + Q_ * DH_;
    float* sS  = sKV + B_ * 65;

    const int blk = blockIdx.x;
    const int s = blk / (N_ * HEADS_);
    const int n = (blk / HEADS_) % N_;
    const int h = blk % HEADS_;
    const int tid = threadIdx.x;

    for (int t = tid; t < Q_ * DH_; t += 256) {
        int qi = t >> 6, d = t & 63;
        sQ[t] = q[qi * INNER_ + h * DH_ + d];
    }
    const float* kvbase = g_kv + ((size_t)(s * N_ + n)) * B_ * KVW_;
    for (int t = tid; t < B_ * DH_; t += 256) {
        int j = t >> 6, d = t & 63;
        sKV[j * 65 + d] = kvbase[(size_t)j * KVW_ + h * DH_ + d];
    }
    __syncthreads();

    for (int t = tid; t < Q_ * B_; t += 256) {
        int qi = t >> 7, j = t & 127;
        const float* qp = sQ + qi * DH_;
        const float* kp = sKV + j * 65;
        float a = 0.f;
        #pragma unroll
        for (int d = 0; d < DH_; d++) a += qp[d] * kp[d];
        a *= 0.125f;
        if (mask[s * B_ + j] == 0) a = -1e10f;
        sS[qi * 128 + j] = a;
    }
    __syncthreads();

    const int warp = tid >> 5, lane = tid & 31;
    for (int r = warp * 8; r < warp * 8 + 8; r++) {
        float* row = sS + r * 128;
        float v0 = row[lane], v1 = row[lane + 32], v2 = row[lane + 64], v3 = row[lane + 96];
        float mx = fmaxf(fmaxf(v0, v1), fmaxf(v2, v3));
        #pragma unroll
        for (int o = 16; o > 0; o >>= 1) mx = fmaxf(mx, __shfl_xor_sync(0xffffffffu, mx, o));
        v0 = expf(v0 - mx); v1 = expf(v1 - mx); v2 = expf(v2 - mx); v3 = expf(v3 - mx);
        float sum = v0 + v1 + v2 + v3;
        #pragma unroll
        for (int o = 16; o > 0; o >>= 1) sum += __shfl_xor_sync(0xffffffffu, sum, o);
        float inv = 1.0f / sum;
        row[lane] = v0 * inv; row[lane + 32] = v1 * inv;
        row[lane + 64] = v2 * inv; row[lane + 96] = v3 * inv;
    }
    __syncthreads();

    for (int t = tid; t < B_ * DH_; t += 256) {
        int j = t >> 6, d = t & 63;
        sKV[j * 65 + d] = kvbase[(size_t)j * KVW_ + INNER_ + h * DH_ + d];
    }
    __syncthreads();

    float* outbase = g_att + ((size_t)(s * N_ + n)) * Q_ * INNER_;
    for (int t = tid; t < Q_ * DH_; t += 256) {
        int qi = t >> 6, d = t & 63;
        const float* ar = sS + qi * 128;
        float a = 0.f;
        #pragma unroll
        for (int j = 0; j < B_; j++) a += ar[j] * sKV[j * 65 + d];
        outbase[(size_t)qi * INNER_ + h * DH_ + d] = a;
    }
}

// ---------------- LayerNorm (fp32 y + bf16 hi/lo) ----------------
__global__ __launch_bounds__(256) void ln_kernel(
    const float* __restrict__ gamma, const float* __restrict__ beta)
{
    const int r = blockIdx.x;
    const float* xr = g_att + (size_t)r * INNER_;
    float* yr = g_y + (size_t)r * INNER_;
    const int tid = threadIdx.x;
    const int warp = tid >> 5, lane = tid & 31;

    float v[4];
    float sum = 0.f;
    #pragma unroll
    for (int i = 0; i < 4; i++) { v[i] = xr[tid + i * 256]; sum += v[i]; }

    __shared__ float red[8];
    #pragma unroll
    for (int o = 16; o > 0; o >>= 1) sum += __shfl_xor_sync(0xffffffffu, sum, o);
    if (lane == 0) red[warp] = sum;
    __syncthreads();
    float tot = red[lane & 7];
    #pragma unroll
    for (int o = 4; o > 0; o >>= 1) tot += __shfl_xor_sync(0xffffffffu, tot, o);
    float mean = tot * (1.0f / 1024.0f);

    float sq = 0.f;
    #pragma unroll
    for (int i = 0; i < 4; i++) { float d = v[i] - mean; sq += d * d; }
    #pragma unroll
    for (int o = 16; o > 0; o >>= 1) sq += __shfl_xor_sync(0xffffffffu, sq, o);
    __syncthreads();
    if (lane == 0) red[warp] = sq;
    __syncthreads();
    float tot2 = red[lane & 7];
    #pragma unroll
    for (int o = 4; o > 0; o >>= 1) tot2 += __shfl_xor_sync(0xffffffffu, tot2, o);
    float var = tot2 * (1.0f / 1024.0f);
    float inv = rsqrtf(var + 1e-5f);

    #pragma unroll
    for (int i = 0; i < 4; i++) {
        int c = tid + i * 256;
        float yv = (v[i] - mean) * inv * gamma[c] + beta[c];
        yr[c] = yv;
        __nv_bfloat16 h, l;
        split2(yv, h, l);
        g_y_hi[(size_t)r * INNER_ + c] = h;
        g_y_lo[(size_t)r * INNER_ + c] = l;
    }
}

// ---------------- GEGLU ----------------
__global__ __launch_bounds__(256) void geglu_kernel()
{
    const size_t i = (size_t)blockIdx.x * 256 + threadIdx.x;
    const size_t e = i << 2;
    const size_t r = e >> 12;
    const int c = (int)(e & 4095);
    const float4 a = *(const float4*)(g_u + r * FF2_ + c);
    const float4 g = *(const float4*)(g_u + r * FF2_ + FFH_ + c);
    float vals[4];
    vals[0] = a.x * (0.5f * g.x * (1.0f + erff(g.x * 0.70710678118654752f)));
    vals[1] = a.y * (0.5f * g.y * (1.0f + erff(g.y * 0.70710678118654752f)));
    vals[2] = a.z * (0.5f * g.z * (1.0f + erff(g.z * 0.70710678118654752f)));
    vals[3] = a.w * (0.5f * g.w * (1.0f + erff(g.w * 0.70710678118654752f)));
    __nv_bfloat16 h0, l0, h1, l1, h2, l2, h3, l3;
    split2(vals[0], h0, l0); split2(vals[1], h1, l1);
    split2(vals[2], h2, l2); split2(vals[3], h3, l3);
    *(__nv_bfloat162*)(g_h_hi + e)     = __halves2bfloat162(h0, h1);
    *(__nv_bfloat162*)(g_h_hi + e + 2) = __halves2bfloat162(h2, h3);
    *(__nv_bfloat162*)(g_h_lo + e)     = __halves2bfloat162(l0, l1);
    *(__nv_bfloat162*)(g_h_lo + e + 2) = __halves2bfloat162(l2, l3);
}

// ---------------- launch ----------------
extern "C" void kernel_launch(void* const* d_in, const int* in_sizes, int n_in,
                              void* d_out, int out_size)
{
    const float* x    = (const float*)d_in[0];
    const int*   mask = (const int*)  d_in[1];
    const float* q    = (const float*)d_in[2];
    const float* W_kv = (const float*)d_in[3];
    const float* ln_g = (const float*)d_in[4];
    const float* ln_b = (const float*)d_in[5];
    const float* W1   = (const float*)d_in[6];
    const float* b1   = (const float*)d_in[7];
    const float* W2   = (const float*)d_in[8];
    const float* b2   = (const float*)d_in[9];
    float* out = (float*)d_out;
    (void)in_sizes; (void)n_in; (void)out_size;

    float *kv, *y, *u;
    __nv_bfloat16 *xah, *xal, *wkh, *wkl, *w1h, *w1l, *w2h, *w2l, *yh, *yl, *hh, *hl;
    cudaGetSymbolAddress((void**)&kv,  g_kv);
    cudaGetSymbolAddress((void**)&y,   g_y);
    cudaGetSymbolAddress((void**)&u,   g_u);
    cudaGetSymbolAddress((void**)&xah, g_xa_hi);
    cudaGetSymbolAddress((void**)&xal, g_xa_lo);
    cudaGetSymbolAddress((void**)&wkh, g_wkt_hi);
    cudaGetSymbolAddress((void**)&wkl, g_wkt_lo);
    cudaGetSymbolAddress((void**)&w1h, g_w1t_hi);
    cudaGetSymbolAddress((void**)&w1l, g_w1t_lo);
    cudaGetSymbolAddress((void**)&w2h, g_w2t_hi);
    cudaGetSymbolAddress((void**)&w2l, g_w2t_lo);
    cudaGetSymbolAddress((void**)&yh,  g_y_hi);
    cudaGetSymbolAddress((void**)&yl,  g_y_lo);
    cudaGetSymbolAddress((void**)&hh,  g_h_hi);
    cudaGetSymbolAddress((void**)&hl,  g_h_lo);

    cudaFuncSetAttribute(attn_kernel, cudaFuncAttributeMaxDynamicSharedMemorySize, ATTN_SMEM);
    cudaFuncSetAttribute(mma_gemm,    cudaFuncAttributeMaxDynamicSharedMemorySize, GEMM_SMEM);

    // prep: split/transpose
    prep_x_kernel<<<(KVROWS_ * (size_t)D_) / 4 / 256, 256>>>(x);
    {
        dim3 b(32, 8);
        tsplit_kernel<<<dim3(KVW_ / 32, D_ / 32), b>>>(W_kv, wkh, wkl, D_, KVW_);
        tsplit_kernel<<<dim3(FF2_ / 32, INNER_ / 32), b>>>(W1, w1h, w1l, INNER_, FF2_);
        tsplit_kernel<<<dim3(INNER_ / 32, FFH_ / 32), b>>>(W2, w2h, w2l, FFH_, INNER_);
    }
    // 1) kv = x_t @ W_kv    (32768 x 2048, K=1024)
    mma_gemm<<<dim3(KVW_ / 128, KVROWS_ / 128), 256, GEMM_SMEM>>>(
        xah, xal, wkh, wkl, kv, KVW_, D_, 0, nullptr, nullptr);
    // 2) attention -> g_att
    attn_kernel<<<S_ * N_ * HEADS_, 256, ATTN_SMEM>>>(q, mask);
    // 3) LayerNorm -> g_y (+ bf16 hi/lo)
    ln_kernel<<<ROWS_, 256>>>(ln_g, ln_b);
    // 4) u = y @ W1 + b1    (16384 x 8192, K=1024)
    mma_gemm<<<dim3(FF2_ / 128, ROWS_ / 128), 256, GEMM_SMEM>>>(
        yh, yl, w1h, w1l, u, FF2_, INNER_, 1, b1, nullptr);
    // 5) geglu -> h hi/lo
    geglu_kernel<<<(ROWS_ * (size_t)FFH_) / 4 / 256, 256>>>();
    // 6) out = h @ W2 + b2 + y  (16384 x 1024, K=4096)
    mma_gemm<<<dim3(INNER_ / 128, ROWS_ / 128), 256, GEMM_SMEM>>>(
        hh, hl, w2h, w2l, out, INNER_, FFH_, 2, b2, y);
}